// round 10
// baseline (speedup 1.0000x reference)
#include <cuda_runtime.h>
#include <cstdint>

#define TSEQ 1024
#define EDIM 256
#define EH   2048
#define ROWS 8192

// ---------------- scratch ----------------
__device__ __align__(16) float g_xr[ROWS * (size_t)EDIM];        // tf32-rounded x
__device__ __align__(16) float g_q [ROWS * (size_t)EH];
__device__ __align__(16) float g_k [ROWS * (size_t)EH];
__device__ __align__(16) float g_vt[64 * (size_t)EDIM * TSEQ];   // [bh][n][j] (tf32-rounded)
__device__ __align__(16) float g_o [ROWS * (size_t)EH];
__device__ __align__(16) float g_wt[4 * (size_t)EH * EDIM];      // WqT,WkT,WvT,WuT (K-contig)

// ---------------- helpers ----------------
__device__ __forceinline__ float f2tf32f(float f) {
    uint32_t u; asm("cvt.rna.tf32.f32 %0, %1;" : "=r"(u) : "f"(f));
    return __uint_as_float(u);
}
__device__ __forceinline__ uint32_t smem_u32(const void* p) {
    uint32_t a;
    asm("{ .reg .u64 t; cvta.to.shared.u64 t, %1; cvt.u32.u64 %0, t; }" : "=r"(a) : "l"(p));
    return a;
}
__device__ __forceinline__ void mma_tf32(float* c, const uint32_t* a, const uint32_t* b) {
    asm volatile("mma.sync.aligned.m16n8k8.row.col.f32.tf32.tf32.f32 "
                 "{%0,%1,%2,%3}, {%4,%5,%6,%7}, {%8,%9}, {%0,%1,%2,%3};"
                 : "+f"(c[0]), "+f"(c[1]), "+f"(c[2]), "+f"(c[3])
                 : "r"(a[0]), "r"(a[1]), "r"(a[2]), "r"(a[3]), "r"(b[0]), "r"(b[1]));
}
#define LDSM_X4(r0, r1, r2, r3, addr) \
    asm volatile("ldmatrix.sync.aligned.m8n8.x4.shared.b16 {%0,%1,%2,%3}, [%4];" \
                 : "=r"(r0), "=r"(r1), "=r"(r2), "=r"(r3) : "r"(addr))
#define CP16(dst, src) \
    asm volatile("cp.async.cg.shared.global [%0], [%1], 16;" :: "r"(dst), "l"(src))
#define CP_COMMIT()  asm volatile("cp.async.commit_group;")
#define CP_WAIT1()   asm volatile("cp.async.wait_group 1;")
#define CP_WAIT0()   asm volatile("cp.async.wait_group 0;")

// BK=32 tile row: 128 B, 8x16B chunks, 8-way XOR swizzle
#define STAGES    2
#define STAGE_B   32768            // A 16 KB + B 16 KB (128-row tiles)
#define SMEM_BYTES (STAGES * STAGE_B)   // 64 KB for plain GEMM kernels

// ====== plain GEMM machinery (128 threads, 4 warps, warp 64x64) — proven R9 ======
__device__ __forceinline__ void issue_stage(uint32_t sb, int s,
                                            const float* __restrict__ A, int lda,
                                            const float* __restrict__ B, int ldb,
                                            int k0, int tid)
{
    const uint32_t abase = sb + s * STAGE_B;
    const uint32_t bbase = abase + 16384;
    const int r0 = tid >> 3;
    const int c  = tid & 7;
    const float* asrc = A + (size_t)r0 * lda + k0 + c * 4;
    const float* bsrc = B + (size_t)r0 * ldb + k0 + c * 4;
    #pragma unroll
    for (int w = 0; w < 8; ++w) {
        const int row = w * 16 + r0;
        const uint32_t off = (uint32_t)(row * 128 + ((c ^ (row & 7)) << 4));
        CP16(abase + off, asrc + (size_t)w * 16 * lda);
        CP16(bbase + off, bsrc + (size_t)w * 16 * ldb);
    }
    CP_COMMIT();
}

// generic 64x64-warp-tile compute: A at abase (128 rows), B at bbase (rows addressed up to 256)
__device__ __forceinline__ void compute_64x64(uint32_t abase, uint32_t bbase,
                                              float acc[4][8][4], int wm, int wn, int lane)
{
    const int arow = wm * 64 + (lane & 15);
    const int ahi  = (lane >> 4) & 1;
    const int brow0 = wn * 64 + (lane & 7);
    const int bci  = lane >> 3;

    #pragma unroll
    for (int kp = 0; kp < 2; ++kp) {
        uint32_t bf[8][4];
        #pragma unroll
        for (int nt = 0; nt < 8; ++nt) {
            const int r = brow0 + nt * 8;
            const uint32_t ad = bbase + (uint32_t)(r * 128 + (((kp * 4 + bci) ^ (r & 7)) << 4));
            LDSM_X4(bf[nt][0], bf[nt][1], bf[nt][2], bf[nt][3], ad);
        }
        #pragma unroll
        for (int ks = 0; ks < 2; ++ks) {
            const int ksg = kp * 2 + ks;
            uint32_t af[4][4];
            #pragma unroll
            for (int mt = 0; mt < 4; ++mt) {
                const int r = arow + mt * 16;
                const uint32_t ad = abase + (uint32_t)(r * 128 + (((ksg * 2 + ahi) ^ (r & 7)) << 4));
                LDSM_X4(af[mt][0], af[mt][1], af[mt][2], af[mt][3], ad);
            }
            #pragma unroll
            for (int mt = 0; mt < 4; ++mt)
                #pragma unroll
                for (int nt = 0; nt < 8; ++nt)
                    mma_tf32(acc[mt][nt], af[mt], &bf[nt][ks * 2]);
        }
    }
}

__device__ __forceinline__ void gemm_mma(const float* __restrict__ A, int lda,
                                         const float* __restrict__ B, int ldb,
                                         int K, float acc[4][8][4], uint32_t sb)
{
    const int tid = threadIdx.x;
    const int wid = tid >> 5, lane = tid & 31;
    const int wm = wid & 1, wn = wid >> 1;
    const int KC = K >> 5;

    issue_stage(sb, 0, A, lda, B, ldb, 0, tid);
    int s = 0;
    for (int c = 0; c < KC; ++c) {
        if (c + 1 < KC) {
            __syncthreads();
            issue_stage(sb, s ^ 1, A, lda, B, ldb, (c + 1) * 32, tid);
            CP_WAIT1();
        } else {
            CP_WAIT0();
        }
        __syncthreads();
        const uint32_t ab = sb + s * STAGE_B;
        compute_64x64(ab, ab + 16384, acc, wm, wn, lane);
        s ^= 1;
    }
    __syncthreads();
}

template<int ROUND>
__device__ __forceinline__ void epi_plain(float acc[4][8][4], float* C, int ldc,
                                          const float* bias)
{
    const int wid = threadIdx.x >> 5, lane = threadIdx.x & 31;
    const int wm = wid & 1, wn = wid >> 1;
    #pragma unroll
    for (int mt = 0; mt < 4; ++mt) {
        const int m = wm * 64 + mt * 16 + (lane >> 2);
        #pragma unroll
        for (int nt = 0; nt < 8; ++nt) {
            const int n = wn * 64 + nt * 8 + (lane & 3) * 2;
            float b0 = 0.f, b1 = 0.f;
            if (bias) { b0 = bias[n]; b1 = bias[n + 1]; }
            float v0 = acc[mt][nt][0] + b0, v1 = acc[mt][nt][1] + b1;
            float v2 = acc[mt][nt][2] + b0, v3 = acc[mt][nt][3] + b1;
            if (ROUND) { v0 = f2tf32f(v0); v1 = f2tf32f(v1); v2 = f2tf32f(v2); v3 = f2tf32f(v3); }
            *(float2*)(C + (size_t)m * ldc + n)       = make_float2(v0, v1);
            *(float2*)(C + (size_t)(m + 8) * ldc + n) = make_float2(v2, v3);
        }
    }
}

// ====== fused attention machinery (256 threads, 8 warps) ======
// smem map: P [0,64K) = 4 sub-tiles of 16KB (j-chunks); QK stream [64K,128K) 2x32K;
//           V stream [128K,192K) 2x32K; rs [192K, +512)
#define FA_P   0
#define FA_G1  65536
#define FA_VB  131072
#define FA_RS  196608
#define FA_SMEM 197120

// QK stage: A=Q 128 rows + B=K 128 rows, both lda=EH (256 threads, 4+4 CP16)
__device__ __forceinline__ void issue_qk(uint32_t g1, int s,
                                         const float* __restrict__ A,
                                         const float* __restrict__ B, int k0, int tid)
{
    const uint32_t abase = g1 + s * 32768;
    const uint32_t bbase = abase + 16384;
    const int r0 = tid >> 3;           // 0..31
    const int c  = tid & 7;
    const float* asrc = A + (size_t)r0 * EH + k0 + c * 4;
    const float* bsrc = B + (size_t)r0 * EH + k0 + c * 4;
    #pragma unroll
    for (int w = 0; w < 4; ++w) {
        const int row = w * 32 + r0;
        const uint32_t off = (uint32_t)(row * 128 + ((c ^ (row & 7)) << 4));
        CP16(abase + off, asrc + (size_t)w * 32 * EH);
        CP16(bbase + off, bsrc + (size_t)w * 32 * EH);
    }
    CP_COMMIT();
}

// V stage: 256 rows x 32 j-floats from g_vt (row stride TSEQ)
__device__ __forceinline__ void issue_v(uint32_t vb, int v,
                                        const float* __restrict__ Vtb, int j0, int tid)
{
    const uint32_t base = vb + v * 32768;
    const int r0 = tid >> 3;
    const int c  = tid & 7;
    const float* src = Vtb + (size_t)r0 * TSEQ + j0 + c * 4;
    #pragma unroll
    for (int w = 0; w < 8; ++w) {
        const int row = w * 32 + r0;
        const uint32_t off = (uint32_t)(row * 128 + ((c ^ (row & 7)) << 4));
        CP16(base + off, src + (size_t)w * 32 * TSEQ);
    }
    CP_COMMIT();
}

// GEMM1 compute: warp tile 64x32 (grid 2m x 4n), acc_s[4][4][4]
__device__ __forceinline__ void compute_s(uint32_t stage, float acc[4][4][4],
                                          int wm, int wn, int lane)
{
    const uint32_t abase = stage;
    const uint32_t bbase = stage + 16384;
    const int arow  = wm * 64 + (lane & 15);
    const int ahi   = (lane >> 4) & 1;
    const int brow0 = wn * 32 + (lane & 7);
    const int bci   = lane >> 3;

    #pragma unroll
    for (int kp = 0; kp < 2; ++kp) {
        uint32_t bf[4][4];
        #pragma unroll
        for (int nt = 0; nt < 4; ++nt) {
            const int r = brow0 + nt * 8;
            const uint32_t ad = bbase + (uint32_t)(r * 128 + (((kp * 4 + bci) ^ (r & 7)) << 4));
            LDSM_X4(bf[nt][0], bf[nt][1], bf[nt][2], bf[nt][3], ad);
        }
        #pragma unroll
        for (int ks = 0; ks < 2; ++ks) {
            const int ksg = kp * 2 + ks;
            uint32_t af[4][4];
            #pragma unroll
            for (int mt = 0; mt < 4; ++mt) {
                const int r = arow + mt * 16;
                const uint32_t ad = abase + (uint32_t)(r * 128 + (((ksg * 2 + ahi) ^ (r & 7)) << 4));
                LDSM_X4(af[mt][0], af[mt][1], af[mt][2], af[mt][3], ad);
            }
            #pragma unroll
            for (int mt = 0; mt < 4; ++mt)
                #pragma unroll
                for (int nt = 0; nt < 4; ++nt)
                    mma_tf32(acc[mt][nt], af[mt], &bf[nt][ks * 2]);
        }
    }
}

// fused: per (bh, it): O[128x256] = softmax-unnorm(Q.K^T masked) @ Vt^T, then normalize
__global__ __launch_bounds__(256) void attn_fused()
{
    extern __shared__ __align__(1024) unsigned char sbuf[];
    const uint32_t sb = smem_u32(sbuf);
    float* rs = (float*)(sbuf + FA_RS);

    const int it = 7 - (int)blockIdx.x;      // heaviest blocks first
    const int bh = blockIdx.y, b = bh >> 3, h = bh & 7;
    const int tid = threadIdx.x, wid = tid >> 5, lane = tid & 31;
    const int wm = wid & 1;                  // m-warp (both gemms)
    const int wn = wid >> 1;                 // 0..3  (n-warp both gemms)

    const float* Aq = g_q + (size_t)(b * TSEQ + it * 128) * EH + h * EDIM;
    const float* Vtb = g_vt + (size_t)bh * EDIM * TSEQ;

    float acc_o[4][8][4] = {};
    float rsum_p[4][2] = {};

    for (int jt = 0; jt <= it; ++jt) {
        const float* Bk = g_k + (size_t)(b * TSEQ + jt * 128) * EH + h * EDIM;

        // ---- GEMM1: S = Q . K^T (K=256, 8 stages) ----
        float acc_s[4][4][4] = {};
        issue_qk(sb + FA_G1, 0, Aq, Bk, 0, tid);
        int s = 0;
        for (int c = 0; c < 8; ++c) {
            if (c < 7) {
                __syncthreads();
                issue_qk(sb + FA_G1, s ^ 1, Aq, Bk, (c + 1) * 32, tid);
                CP_WAIT1();
            } else CP_WAIT0();
            __syncthreads();
            compute_s(sb + FA_G1 + s * 32768, acc_s, wm, wn, lane);
            s ^= 1;
        }

        // ---- mask + exp + rowsum + scatter P (each n-warp owns sub-tile wn) ----
        const bool diag = (jt == it);
        #pragma unroll
        for (int mt = 0; mt < 4; ++mt) {
            const int m0 = wm * 64 + mt * 16 + (lane >> 2);
            #pragma unroll
            for (int nt = 0; nt < 4; ++nt) {
                const int n = wn * 32 + nt * 8 + (lane & 3) * 2;   // local j within jt tile
                float e0 = f2tf32f(__expf(acc_s[mt][nt][0] * 0.0625f));
                float e1 = f2tf32f(__expf(acc_s[mt][nt][1] * 0.0625f));
                float e2 = f2tf32f(__expf(acc_s[mt][nt][2] * 0.0625f));
                float e3 = f2tf32f(__expf(acc_s[mt][nt][3] * 0.0625f));
                if (diag) {
                    if (n     >= m0)     e0 = 0.f;
                    if (n + 1 >= m0)     e1 = 0.f;
                    if (n     >= m0 + 8) e2 = 0.f;
                    if (n + 1 >= m0 + 8) e3 = 0.f;
                }
                rsum_p[mt][0] += e0 + e1;
                rsum_p[mt][1] += e2 + e3;
                const int jn = n & 31;               // j within sub-tile (chunk = jn>>2)
                const uint32_t sw = (uint32_t)(((jn >> 2) ^ (m0 & 7)) << 4) + (uint32_t)((n & 3) * 4);
                const uint32_t base = (uint32_t)(FA_P + wn * 16384);
                *(float2*)(sbuf + base + (uint32_t)(m0 * 128) + sw)       = make_float2(e0, e1);
                *(float2*)(sbuf + base + (uint32_t)((m0 + 8) * 128) + sw) = make_float2(e2, e3);
            }
        }

        // ---- GEMM2: O += P . Vt^T (K=128, 4 stages; P resident, V streamed) ----
        issue_v(sb + FA_VB, 0, Vtb, jt * 128, tid);
        int v = 0;
        for (int c = 0; c < 4; ++c) {
            if (c < 3) {
                __syncthreads();     // V-buf reuse + (first iter) P visibility
                issue_v(sb + FA_VB, v ^ 1, Vtb, jt * 128 + (c + 1) * 32, tid);
                CP_WAIT1();
            } else CP_WAIT0();
            __syncthreads();
            compute_64x64(sb + FA_P + c * 16384, sb + FA_VB + v * 32768, acc_o, wm, wn, lane);
            v ^= 1;
        }
    }

    // ---- rowsum reduce + normalize + store ----
    if (tid < 128) rs[tid] = 0.f;
    __syncthreads();
    #pragma unroll
    for (int mt = 0; mt < 4; ++mt)
        #pragma unroll
        for (int half = 0; half < 2; ++half) {
            float r = rsum_p[mt][half];
            r += __shfl_xor_sync(0xffffffffu, r, 1);
            r += __shfl_xor_sync(0xffffffffu, r, 2);
            if ((lane & 3) == 0)
                atomicAdd(&rs[wm * 64 + mt * 16 + (lane >> 2) + half * 8], r);
        }
    __syncthreads();

    float* O = g_o + (size_t)(b * TSEQ + it * 128) * EH + h * EDIM;
    #pragma unroll
    for (int mt = 0; mt < 4; ++mt) {
        const int m = wm * 64 + mt * 16 + (lane >> 2);
        const float s0 = rs[m], s1 = rs[m + 8];
        const float i0 = (s0 > 0.f) ? __fdividef(1.f, s0) : 0.f;
        const float i1 = (s1 > 0.f) ? __fdividef(1.f, s1) : 0.f;
        #pragma unroll
        for (int nt = 0; nt < 8; ++nt) {
            const int n = wn * 64 + nt * 8 + (lane & 3) * 2;
            float v0 = f2tf32f(acc_o[mt][nt][0] * i0), v1 = f2tf32f(acc_o[mt][nt][1] * i0);
            float v2 = f2tf32f(acc_o[mt][nt][2] * i1), v3 = f2tf32f(acc_o[mt][nt][3] * i1);
            *(float2*)(O + (size_t)m * EH + n)       = make_float2(v0, v1);
            *(float2*)(O + (size_t)(m + 8) * EH + n) = make_float2(v2, v3);
        }
    }
}

// ---------------- other kernels (proven) ----------------

__global__ __launch_bounds__(256) void round_x(const float* __restrict__ x)
{
    const size_t i = ((size_t)blockIdx.x * 256 + threadIdx.x) * 4;
    float4 v = *(const float4*)(x + i);
    v.x = f2tf32f(v.x); v.y = f2tf32f(v.y); v.z = f2tf32f(v.z); v.w = f2tf32f(v.w);
    *(float4*)(g_xr + i) = v;
}

__global__ __launch_bounds__(256) void transpose_w(const float* __restrict__ Wq,
                                                   const float* __restrict__ Wk,
                                                   const float* __restrict__ Wv,
                                                   const float* __restrict__ Wu)
{
    const int z = blockIdx.z;
    const float* src; float* dst; int R, C;
    if (z < 3) { src = (z == 0) ? Wq : (z == 1) ? Wk : Wv; dst = g_wt + (size_t)z * 524288; R = EDIM; C = EH; }
    else       { src = Wu; dst = g_wt + 3 * 524288; R = EH; C = EDIM; }
    const int cb = blockIdx.x * 32, rb = blockIdx.y * 32;
    if (cb >= C || rb >= R) return;
    __shared__ float t[32][33];
    const int tx = threadIdx.x & 31, ty = threadIdx.x >> 5;
    #pragma unroll
    for (int i = ty; i < 32; i += 8)
        t[i][tx] = f2tf32f(src[(size_t)(rb + i) * C + cb + tx]);
    __syncthreads();
    #pragma unroll
    for (int i = ty; i < 32; i += 8)
        dst[(size_t)(cb + i) * R + rb + tx] = t[tx][i];
}

__global__ __launch_bounds__(128) void qkv_gemm(const float* __restrict__ bq,
                                                const float* __restrict__ bk,
                                                const float* __restrict__ bv)
{
    extern __shared__ __align__(1024) unsigned char sbuf[];
    const uint32_t sb = smem_u32(sbuf);
    const int z = blockIdx.z, col0 = blockIdx.x * 128, row0 = blockIdx.y * 128;
    const float* A = g_xr + (size_t)row0 * EDIM;
    const float* B = g_wt + (size_t)z * 524288 + (size_t)col0 * EDIM;
    float acc[4][8][4] = {};
    gemm_mma(A, EDIM, B, EDIM, EDIM, acc, sb);

    if (z < 2) {
        float* C = (z == 0 ? g_q : g_k) + (size_t)row0 * EH + col0;
        const float* bias = (z == 0 ? bq : bk) + col0;
        epi_plain<1>(acc, C, EH, bias);
        return;
    }
    // z==2: stage [n][m] in smem (64x132 floats, two halves), coalesced store to g_vt
    const int wid = threadIdx.x >> 5, lane = threadIdx.x & 31;
    const int wm = wid & 1, wn = wid >> 1;
    const int b = row0 >> 10, i0 = row0 & 1023;
    const int vrow0 = (b * 8 + (col0 >> 8)) * 256 + (col0 & 255);
    const float* bias = bv + col0;
    float* st = (float*)sbuf;                 // [64][132]
    #pragma unroll
    for (int hf = 0; hf < 2; ++hf) {
        __syncthreads();
        if (wn == hf) {
            #pragma unroll
            for (int mt = 0; mt < 4; ++mt) {
                const int m = wm * 64 + mt * 16 + (lane >> 2);
                #pragma unroll
                for (int nt = 0; nt < 8; ++nt) {
                    const int nl = nt * 8 + (lane & 3) * 2;
                    const float b0 = bias[hf * 64 + nl], b1 = bias[hf * 64 + nl + 1];
                    st[nl * 132 + m]             = f2tf32f(acc[mt][nt][0] + b0);
                    st[(nl + 1) * 132 + m]       = f2tf32f(acc[mt][nt][1] + b1);
                    st[nl * 132 + m + 8]         = f2tf32f(acc[mt][nt][2] + b0);
                    st[(nl + 1) * 132 + m + 8]   = f2tf32f(acc[mt][nt][3] + b1);
                }
            }
        }
        __syncthreads();
        #pragma unroll
        for (int r = 0; r < 16; ++r) {
            const int nl = wid * 16 + r;
            float4 v = *(float4*)(st + nl * 132 + lane * 4);
            *(float4*)(g_vt + (size_t)(vrow0 + hf * 64 + nl) * TSEQ + i0 + lane * 4) = v;
        }
    }
}

__global__ __launch_bounds__(128) void proj_gemm(const float* __restrict__ bu,
                                                 float* __restrict__ out)
{
    const int col0 = blockIdx.x * 128, row0 = blockIdx.y * 128;
    extern __shared__ __align__(1024) unsigned char sbuf[];
    const uint32_t sb = smem_u32(sbuf);
    const float* A = g_o + (size_t)row0 * EH;
    const float* B = g_wt + 3 * 524288 + (size_t)col0 * EH;
    float acc[4][8][4] = {};
    gemm_mma(A, EH, B, EH, EH, acc, sb);
    epi_plain<0>(acc, out + (size_t)row0 * EDIM + col0, EDIM, bu + col0);
}

// ---------------------------------------------------------------------------
extern "C" void kernel_launch(void* const* d_in, const int* in_sizes, int n_in,
                              void* d_out, int out_size)
{
    (void)in_sizes; (void)n_in; (void)out_size;
    const float* x  = (const float*)d_in[0];
    const float* Wq = (const float*)d_in[1];
    const float* bq = (const float*)d_in[2];
    const float* Wk = (const float*)d_in[3];
    const float* bk = (const float*)d_in[4];
    const float* Wv = (const float*)d_in[5];
    const float* bv = (const float*)d_in[6];
    const float* Wu = (const float*)d_in[7];
    const float* bu = (const float*)d_in[8];
    float* out = (float*)d_out;

    static bool attr_done = false;
    if (!attr_done) {
        cudaFuncSetAttribute(qkv_gemm,   cudaFuncAttributeMaxDynamicSharedMemorySize, SMEM_BYTES);
        cudaFuncSetAttribute(attn_fused, cudaFuncAttributeMaxDynamicSharedMemorySize, FA_SMEM);
        cudaFuncSetAttribute(proj_gemm,  cudaFuncAttributeMaxDynamicSharedMemorySize, SMEM_BYTES);
        attr_done = true;
    }

    round_x    <<<dim3(ROWS * EDIM / 1024), 256>>>(x);
    transpose_w<<<dim3(64, 64, 4), 256>>>(Wq, Wk, Wv, Wu);
    qkv_gemm   <<<dim3(16, 64, 3), 128, SMEM_BYTES>>>(bq, bk, bv);
    attn_fused <<<dim3(8, 64), 256, FA_SMEM>>>();
    proj_gemm  <<<dim3(2, 64, 1), 128, SMEM_BYTES>>>(bu, out);
}

// round 12
// speedup vs baseline: 1.9812x; 1.9812x over previous
#include <cuda_runtime.h>
#include <cuda_fp16.h>
#include <cstdint>

#define TSEQ 1024
#define EDIM 256
#define EH   2048
#define ROWS 8192

// ---------------- scratch (fp16 operands, fp32 stats) ----------------
__device__ __align__(16) __half g_xr[ROWS * (size_t)EDIM];
__device__ __align__(16) __half g_q [ROWS * (size_t)EH];
__device__ __align__(16) __half g_k [ROWS * (size_t)EH];
__device__ __align__(16) __half g_vt[64 * (size_t)EDIM * TSEQ];  // [bh][n][j]
__device__ __align__(16) __half g_s [64LL * TSEQ * TSEQ];        // [bh][i][j] = exp(s/16)
__device__ __align__(16) float  g_rsum[64 * TSEQ];
__device__ __align__(16) __half g_o [ROWS * (size_t)EH];
__device__ __align__(16) __half g_wt[4 * (size_t)EH * EDIM];     // WqT,WkT,WvT,WuT (K-contig)

// ---------------- helpers ----------------
__device__ __forceinline__ uint32_t smem_u32(const void* p) {
    uint32_t a;
    asm("{ .reg .u64 t; cvta.to.shared.u64 t, %1; cvt.u32.u64 %0, t; }" : "=r"(a) : "l"(p));
    return a;
}
__device__ __forceinline__ void mma_f16(float* c, const uint32_t* a, const uint32_t* b) {
    asm volatile("mma.sync.aligned.m16n8k16.row.col.f32.f16.f16.f32 "
                 "{%0,%1,%2,%3}, {%4,%5,%6,%7}, {%8,%9}, {%0,%1,%2,%3};"
                 : "+f"(c[0]), "+f"(c[1]), "+f"(c[2]), "+f"(c[3])
                 : "r"(a[0]), "r"(a[1]), "r"(a[2]), "r"(a[3]), "r"(b[0]), "r"(b[1]));
}
#define LDSM_X4(r0, r1, r2, r3, addr) \
    asm volatile("ldmatrix.sync.aligned.m8n8.x4.shared.b16 {%0,%1,%2,%3}, [%4];" \
                 : "=r"(r0), "=r"(r1), "=r"(r2), "=r"(r3) : "r"(addr))
#define CP16(dst, src) \
    asm volatile("cp.async.cg.shared.global [%0], [%1], 16;" :: "r"(dst), "l"(src))
#define CP_COMMIT()  asm volatile("cp.async.commit_group;")
#define CP_WAIT1()   asm volatile("cp.async.wait_group 1;")
#define CP_WAIT0()   asm volatile("cp.async.wait_group 0;")

__device__ __forceinline__ uint32_t h2u(__half2 h) { return *(uint32_t*)&h; }

// BK=64 stage: 128 rows x 64 halves = 128 B/row, 8x16B chunks, 8-way XOR swizzle
#define STAGES    2
#define STAGE_B   32768            // A 16 KB + B 16 KB
#define SMEM_BYTES (STAGES * STAGE_B)   // 64 KB -> 2 CTAs/SM

// one k-stage (BK=64 halves) of A and B via cp.async (128 threads, 8+8 CP16/thread)
__device__ __forceinline__ void issue_stage(uint32_t sb, int s,
                                            const __half* __restrict__ A, int lda,
                                            const __half* __restrict__ B, int ldb,
                                            int k0, int tid)
{
    const uint32_t abase = sb + s * STAGE_B;
    const uint32_t bbase = abase + 16384;
    const int r0 = tid >> 3;             // 0..15
    const int c  = tid & 7;
    const __half* asrc = A + (size_t)r0 * lda + k0 + c * 8;
    const __half* bsrc = B + (size_t)r0 * ldb + k0 + c * 8;
    #pragma unroll
    for (int w = 0; w < 8; ++w) {
        const int row = w * 16 + r0;
        const uint32_t off = (uint32_t)(row * 128 + ((c ^ (row & 7)) << 4));
        CP16(abase + off, asrc + (size_t)w * 16 * lda);
        CP16(bbase + off, bsrc + (size_t)w * 16 * ldb);
    }
    CP_COMMIT();
}

// compute one BK=64 stage: warp tile 64x64 (warp grid 2m x 2n), m16n8k16 fp16
__device__ __forceinline__ void compute_stage(uint32_t abase, uint32_t bbase,
                                              float acc[4][8][4], int wm, int wn, int lane)
{
    const int arow = wm * 64 + (lane & 15);
    const int achi = lane >> 4;                          // 0/1: +16B (k+8)
    const int brow = wn * 64 + (lane & 7) + ((lane >> 4) << 3);
    const int bchi = (lane >> 3) & 1;                    // 0/1: +16B (k+8)

    #pragma unroll
    for (int ks = 0; ks < 4; ++ks) {                     // k-step = 16 halves = 2 chunks
        uint32_t bf[4][4];                               // bf[np]: n-tiles 2np, 2np+1
        #pragma unroll
        for (int np = 0; np < 4; ++np) {
            const int r = brow + np * 16;
            const uint32_t ad = bbase + (uint32_t)(r * 128 + ((((ks << 1) + bchi) ^ (r & 7)) << 4));
            LDSM_X4(bf[np][0], bf[np][1], bf[np][2], bf[np][3], ad);
        }
        uint32_t af[4][4];
        #pragma unroll
        for (int mt = 0; mt < 4; ++mt) {
            const int r = arow + mt * 16;
            const uint32_t ad = abase + (uint32_t)(r * 128 + ((((ks << 1) + achi) ^ (r & 7)) << 4));
            LDSM_X4(af[mt][0], af[mt][1], af[mt][2], af[mt][3], ad);
        }
        #pragma unroll
        for (int mt = 0; mt < 4; ++mt)
            #pragma unroll
            for (int nt = 0; nt < 8; ++nt)
                mma_f16(acc[mt][nt], af[mt], &bf[nt >> 1][(nt & 1) * 2]);
    }
}

// D[128x128] = A[128xK] . B[128xK]^T  (halves, K multiple of 64; double-buffered)
__device__ __forceinline__ void gemm_mma(const __half* __restrict__ A, int lda,
                                         const __half* __restrict__ B, int ldb,
                                         int K, float acc[4][8][4], uint32_t sb)
{
    const int tid = threadIdx.x;
    const int wid = tid >> 5, lane = tid & 31;
    const int wm = wid & 1, wn = wid >> 1;
    const int KC = K >> 6;

    issue_stage(sb, 0, A, lda, B, ldb, 0, tid);
    int s = 0;
    for (int c = 0; c < KC; ++c) {
        if (c + 1 < KC) {
            __syncthreads();
            issue_stage(sb, s ^ 1, A, lda, B, ldb, (c + 1) * 64, tid);
            CP_WAIT1();
        } else {
            CP_WAIT0();
        }
        __syncthreads();
        const uint32_t ab = sb + s * STAGE_B;
        compute_stage(ab, ab + 16384, acc, wm, wn, lane);
        s ^= 1;
    }
    __syncthreads();
}

// epilogue storing __half (bias fp32 optional)
__device__ __forceinline__ void epi_half(float acc[4][8][4], __half* C, int ldc,
                                         const float* bias)
{
    const int wid = threadIdx.x >> 5, lane = threadIdx.x & 31;
    const int wm = wid & 1, wn = wid >> 1;
    #pragma unroll
    for (int mt = 0; mt < 4; ++mt) {
        const int m = wm * 64 + mt * 16 + (lane >> 2);
        #pragma unroll
        for (int nt = 0; nt < 8; ++nt) {
            const int n = wn * 64 + nt * 8 + (lane & 3) * 2;
            float b0 = 0.f, b1 = 0.f;
            if (bias) { b0 = bias[n]; b1 = bias[n + 1]; }
            *(__half2*)(C + (size_t)m * ldc + n) =
                __floats2half2_rn(acc[mt][nt][0] + b0, acc[mt][nt][1] + b1);
            *(__half2*)(C + (size_t)(m + 8) * ldc + n) =
                __floats2half2_rn(acc[mt][nt][2] + b0, acc[mt][nt][3] + b1);
        }
    }
}

// epilogue storing float (proj)
__device__ __forceinline__ void epi_float(float acc[4][8][4], float* C, int ldc,
                                          const float* bias)
{
    const int wid = threadIdx.x >> 5, lane = threadIdx.x & 31;
    const int wm = wid & 1, wn = wid >> 1;
    #pragma unroll
    for (int mt = 0; mt < 4; ++mt) {
        const int m = wm * 64 + mt * 16 + (lane >> 2);
        #pragma unroll
        for (int nt = 0; nt < 8; ++nt) {
            const int n = wn * 64 + nt * 8 + (lane & 3) * 2;
            const float b0 = bias[n], b1 = bias[n + 1];
            *(float2*)(C + (size_t)m * ldc + n) =
                make_float2(acc[mt][nt][0] + b0, acc[mt][nt][1] + b1);
            *(float2*)(C + (size_t)(m + 8) * ldc + n) =
                make_float2(acc[mt][nt][2] + b0, acc[mt][nt][3] + b1);
        }
    }
}

// ---------------- kernels ----------------

__global__ __launch_bounds__(256) void round_x(const float* __restrict__ x)
{
    const size_t i = ((size_t)blockIdx.x * 256 + threadIdx.x) * 4;
    float4 v = *(const float4*)(x + i);
    uint2 u = { h2u(__floats2half2_rn(v.x, v.y)), h2u(__floats2half2_rn(v.z, v.w)) };
    *(uint2*)(g_xr + i) = u;
}

__global__ __launch_bounds__(256) void transpose_w(const float* __restrict__ Wq,
                                                   const float* __restrict__ Wk,
                                                   const float* __restrict__ Wv,
                                                   const float* __restrict__ Wu)
{
    const int z = blockIdx.z;
    const float* src; __half* dst; int R, C;
    if (z < 3) { src = (z == 0) ? Wq : (z == 1) ? Wk : Wv; dst = g_wt + (size_t)z * 524288; R = EDIM; C = EH; }
    else       { src = Wu; dst = g_wt + 3 * 524288; R = EH; C = EDIM; }
    const int cb = blockIdx.x * 32, rb = blockIdx.y * 32;
    if (cb >= C || rb >= R) return;
    __shared__ float t[32][33];
    const int tx = threadIdx.x & 31, ty = threadIdx.x >> 5;
    #pragma unroll
    for (int i = ty; i < 32; i += 8)
        t[i][tx] = src[(size_t)(rb + i) * C + cb + tx];
    __syncthreads();
    #pragma unroll
    for (int i = ty; i < 32; i += 8)
        dst[(size_t)(cb + i) * R + rb + tx] = __float2half_rn(t[tx][i]);
}

// 1) QKV. z<2 -> g_q/g_k; z==2 -> V transposed into g_vt via smem staging.
__global__ __launch_bounds__(128) void qkv_gemm(const float* __restrict__ bq,
                                                const float* __restrict__ bk,
                                                const float* __restrict__ bv)
{
    extern __shared__ __align__(1024) unsigned char sbuf[];
    const uint32_t sb = smem_u32(sbuf);
    const int z = blockIdx.z, col0 = blockIdx.x * 128, row0 = blockIdx.y * 128;
    const __half* A = g_xr + (size_t)row0 * EDIM;
    const __half* B = g_wt + (size_t)z * 524288 + (size_t)col0 * EDIM;
    float acc[4][8][4] = {};
    gemm_mma(A, EDIM, B, EDIM, EDIM, acc, sb);

    if (z < 2) {
        __half* C = (z == 0 ? g_q : g_k) + (size_t)row0 * EH + col0;
        const float* bias = (z == 0 ? bq : bk) + col0;
        epi_half(acc, C, EH, bias);
        return;
    }
    // z==2: stage [n][m] in smem (64x132 floats, two halves), then half-store to g_vt
    const int wid = threadIdx.x >> 5, lane = threadIdx.x & 31;
    const int wm = wid & 1, wn = wid >> 1;
    const int b = row0 >> 10, i0 = row0 & 1023;
    const int vrow0 = (b * 8 + (col0 >> 8)) * 256 + (col0 & 255);
    const float* bias = bv + col0;
    float* st = (float*)sbuf;                 // [64][132]
    #pragma unroll
    for (int hf = 0; hf < 2; ++hf) {
        __syncthreads();
        if (wn == hf) {
            #pragma unroll
            for (int mt = 0; mt < 4; ++mt) {
                const int m = wm * 64 + mt * 16 + (lane >> 2);
                #pragma unroll
                for (int nt = 0; nt < 8; ++nt) {
                    const int nl = nt * 8 + (lane & 3) * 2;
                    const float b0 = bias[hf * 64 + nl], b1 = bias[hf * 64 + nl + 1];
                    st[nl * 132 + m]             = acc[mt][nt][0] + b0;
                    st[(nl + 1) * 132 + m]       = acc[mt][nt][1] + b1;
                    st[nl * 132 + m + 8]         = acc[mt][nt][2] + b0;
                    st[(nl + 1) * 132 + m + 8]   = acc[mt][nt][3] + b1;
                }
            }
        }
        __syncthreads();
        #pragma unroll
        for (int r = 0; r < 16; ++r) {
            const int nl = wid * 16 + r;
            float4 v = *(float4*)(st + nl * 132 + lane * 4);
            uint2 u = { h2u(__floats2half2_rn(v.x, v.y)), h2u(__floats2half2_rn(v.z, v.w)) };
            *(uint2*)(g_vt + (size_t)(vrow0 + hf * 64 + nl) * TSEQ + i0 + lane * 4) = u;
        }
    }
}

// 2) scores: store exp(Q.K/16) as half, zeros in masked region of diagonal tiles
__global__ __launch_bounds__(128) void scores_gemm()
{
    const int jt = blockIdx.x, it = blockIdx.y, bh = blockIdx.z;
    if (jt > it) return;
    extern __shared__ __align__(1024) unsigned char sbuf[];
    const uint32_t sb = smem_u32(sbuf);
    const int b = bh >> 3, h = bh & 7;
    const __half* A = g_q + (size_t)(b * TSEQ + it * 128) * EH + h * EDIM;
    const __half* B = g_k + (size_t)(b * TSEQ + jt * 128) * EH + h * EDIM;
    float acc[4][8][4] = {};
    gemm_mma(A, EH, B, EH, EDIM, acc, sb);

    __half* C = g_s + ((size_t)bh << 20) + (size_t)(it * 128) * TSEQ + jt * 128;
    const int wid = threadIdx.x >> 5, lane = threadIdx.x & 31;
    const int wm = wid & 1, wn = wid >> 1;
    const bool full = (jt < it);
    #pragma unroll
    for (int mt = 0; mt < 4; ++mt) {
        const int m = wm * 64 + mt * 16 + (lane >> 2);
        #pragma unroll
        for (int nt = 0; nt < 8; ++nt) {
            const int n = wn * 64 + nt * 8 + (lane & 3) * 2;
            float e0 = __expf(acc[mt][nt][0] * 0.0625f);
            float e1 = __expf(acc[mt][nt][1] * 0.0625f);
            float e2 = __expf(acc[mt][nt][2] * 0.0625f);
            float e3 = __expf(acc[mt][nt][3] * 0.0625f);
            if (!full) {                       // diagonal: local mask n<m
                if (n >= m)         e0 = 0.f;
                if (n + 1 >= m)     e1 = 0.f;
                if (n >= m + 8)     e2 = 0.f;
                if (n + 1 >= m + 8) e3 = 0.f;
            }
            *(__half2*)(C + (size_t)m * TSEQ + n)       = __floats2half2_rn(e0, e1);
            *(__half2*)(C + (size_t)(m + 8) * TSEQ + n) = __floats2half2_rn(e2, e3);
        }
    }
}

// 3) rowsum over half P (sums EXACTLY the values GEMM2 consumes)
__global__ __launch_bounds__(256) void rowsum_kernel()
{
    const int wid = threadIdx.x >> 5, lane = threadIdx.x & 31;
    const int r = blockIdx.x * 8 + wid;
    const int i = r & (TSEQ - 1);
    const int klim = ((i >> 7) + 1) << 7;
    const __half* p = g_s + (size_t)r * TSEQ;
    float s = 0.f;
    for (int jb = lane * 8; jb < klim; jb += 256) {
        uint4 u = *(const uint4*)(p + jb);
        float2 f0 = __half22float2(*(__half2*)&u.x);
        float2 f1 = __half22float2(*(__half2*)&u.y);
        float2 f2 = __half22float2(*(__half2*)&u.z);
        float2 f3 = __half22float2(*(__half2*)&u.w);
        s += (f0.x + f0.y) + (f1.x + f1.y) + (f2.x + f2.y) + (f3.x + f3.y);
    }
    #pragma unroll
    for (int d = 16; d > 0; d >>= 1) s += __shfl_xor_sync(0xffffffffu, s, d);
    if (lane == 0) g_rsum[r] = s;
}

// 4) attnv: O = (P_unnorm @ Vt^T) * inv_rowsum, K clipped, half store for proj
__global__ __launch_bounds__(128) void attnv_gemm()
{
    const int nt0 = blockIdx.x, it = blockIdx.y, bh = blockIdx.z;
    extern __shared__ __align__(1024) unsigned char sbuf[];
    const uint32_t sb = smem_u32(sbuf);
    const int b = bh >> 3, h = bh & 7;
    const __half* A = g_s + ((size_t)bh << 20) + (size_t)(it * 128) * TSEQ;
    const __half* B = g_vt + ((size_t)bh * EDIM + nt0 * 128) * TSEQ;
    float acc[4][8][4] = {};
    gemm_mma(A, TSEQ, B, TSEQ, (it + 1) * 128, acc, sb);

    __half* C = g_o + (size_t)(b * TSEQ + it * 128) * EH + h * EDIM + nt0 * 128;
    const float* rs = g_rsum + bh * TSEQ + it * 128;
    const int wid = threadIdx.x >> 5, lane = threadIdx.x & 31;
    const int wm = wid & 1, wn = wid >> 1;
    #pragma unroll
    for (int mt = 0; mt < 4; ++mt) {
        const int m = wm * 64 + mt * 16 + (lane >> 2);
        const float s0 = rs[m], s1 = rs[m + 8];
        const float i0 = (s0 > 0.f) ? __fdividef(1.f, s0) : 0.f;
        const float i1 = (s1 > 0.f) ? __fdividef(1.f, s1) : 0.f;
        #pragma unroll
        for (int nt = 0; nt < 8; ++nt) {
            const int n = wn * 64 + nt * 8 + (lane & 3) * 2;
            *(__half2*)(C + (size_t)m * EH + n) =
                __floats2half2_rn(acc[mt][nt][0] * i0, acc[mt][nt][1] * i0);
            *(__half2*)(C + (size_t)(m + 8) * EH + n) =
                __floats2half2_rn(acc[mt][nt][2] * i1, acc[mt][nt][3] * i1);
        }
    }
}

// 5) proj (fp32 out)
__global__ __launch_bounds__(128) void proj_gemm(const float* __restrict__ bu,
                                                 float* __restrict__ out)
{
    const int col0 = blockIdx.x * 128, row0 = blockIdx.y * 128;
    extern __shared__ __align__(1024) unsigned char sbuf[];
    const uint32_t sb = smem_u32(sbuf);
    const __half* A = g_o + (size_t)row0 * EH;
    const __half* B = g_wt + 3 * 524288 + (size_t)col0 * EH;
    float acc[4][8][4] = {};
    gemm_mma(A, EH, B, EH, EH, acc, sb);
    epi_float(acc, out + (size_t)row0 * EDIM + col0, EDIM, bu + col0);
}

// ---------------------------------------------------------------------------
extern "C" void kernel_launch(void* const* d_in, const int* in_sizes, int n_in,
                              void* d_out, int out_size)
{
    (void)in_sizes; (void)n_in; (void)out_size;
    const float* x  = (const float*)d_in[0];
    const float* Wq = (const float*)d_in[1];
    const float* bq = (const float*)d_in[2];
    const float* Wk = (const float*)d_in[3];
    const float* bk = (const float*)d_in[4];
    const float* Wv = (const float*)d_in[5];
    const float* bv = (const float*)d_in[6];
    const float* Wu = (const float*)d_in[7];
    const float* bu = (const float*)d_in[8];
    float* out = (float*)d_out;

    static bool attr_done = false;
    if (!attr_done) {
        cudaFuncSetAttribute(qkv_gemm,   cudaFuncAttributeMaxDynamicSharedMemorySize, SMEM_BYTES);
        cudaFuncSetAttribute(scores_gemm,cudaFuncAttributeMaxDynamicSharedMemorySize, SMEM_BYTES);
        cudaFuncSetAttribute(attnv_gemm, cudaFuncAttributeMaxDynamicSharedMemorySize, SMEM_BYTES);
        cudaFuncSetAttribute(proj_gemm,  cudaFuncAttributeMaxDynamicSharedMemorySize, SMEM_BYTES);
        attr_done = true;
    }

    round_x       <<<dim3(ROWS * EDIM / 1024), 256>>>(x);
    transpose_w   <<<dim3(64, 64, 4), 256>>>(Wq, Wk, Wv, Wu);
    qkv_gemm      <<<dim3(16, 64, 3), 128, SMEM_BYTES>>>(bq, bk, bv);
    scores_gemm   <<<dim3(8, 8, 64), 128, SMEM_BYTES>>>();
    rowsum_kernel <<<dim3(64 * TSEQ / 8), 256>>>();
    attnv_gemm    <<<dim3(2, 8, 64), 128, SMEM_BYTES>>>();
    proj_gemm     <<<dim3(2, 64, 1), 128, SMEM_BYTES>>>(bu, out);
}